// round 1
// baseline (speedup 1.0000x reference)
#include <cuda_runtime.h>
#include <math.h>

// Problem constants (fixed by the dataset): N=100000, E=800000, D=128, H=4, DH=32
#define MAX_N 100096
#define ND ((size_t)MAX_N * 128)

// Scratch: __device__ globals (allocation-free rule)
__device__ float g_Q[ND];
__device__ float g_K[ND];
__device__ float g_V[ND];
__device__ float g_Y[ND];

// ---------------------------------------------------------------------------
// Fused QKV projection: out[n][(f&3)*32 + (f>>2)] = alpha * (x[n]·W[f] + b[f])
// Head-major layout: feature f = dh*4 + h  ->  stored at h*32 + dh.
// blockIdx.y selects {Q (alpha=0.5), K, V}.
// Tile: 128 rows x 128 cols per CTA, 256 threads, 8x8 microtile, K-chunks of 32.
// ---------------------------------------------------------------------------
__global__ __launch_bounds__(256) void qkv_gemm(
    const float* __restrict__ x,
    const float* __restrict__ Wq, const float* __restrict__ bq,
    const float* __restrict__ Wk, const float* __restrict__ bk,
    const float* __restrict__ Wv, const float* __restrict__ bv,
    int Nn)
{
    __shared__ float Ast[32][128];
    __shared__ float Wst[32][128];

    const float* W; const float* bias; float* out; float alpha;
    switch (blockIdx.y) {
        case 0:  W = Wq; bias = bq; out = g_Q; alpha = 0.5f; break;   // / sqrt(H)
        case 1:  W = Wk; bias = bk; out = g_K; alpha = 1.0f; break;
        default: W = Wv; bias = bv; out = g_V; alpha = 1.0f; break;
    }

    const int m0  = blockIdx.x * 128;
    const int tid = threadIdx.x;
    const int tx  = tid & 15;    // col group (8 cols)
    const int ty  = tid >> 4;    // row group (8 rows)
    const int lid = tid & 127;   // element (m or f) for loads
    const int kq  = (tid >> 7) * 16;

    float acc[8][8];
    #pragma unroll
    for (int i = 0; i < 8; i++)
        #pragma unroll
        for (int j = 0; j < 8; j++) acc[i][j] = 0.f;

    for (int k0 = 0; k0 < 128; k0 += 32) {
        #pragma unroll
        for (int it = 0; it < 4; it++) {
            const int kk = kq + it * 4;
            float4 a4 = make_float4(0.f, 0.f, 0.f, 0.f);
            if (m0 + lid < Nn)
                a4 = *(const float4*)&x[(size_t)(m0 + lid) * 128 + k0 + kk];
            Ast[kk + 0][lid] = a4.x; Ast[kk + 1][lid] = a4.y;
            Ast[kk + 2][lid] = a4.z; Ast[kk + 3][lid] = a4.w;
            const float4 w4 = *(const float4*)&W[(size_t)lid * 128 + k0 + kk];
            Wst[kk + 0][lid] = w4.x; Wst[kk + 1][lid] = w4.y;
            Wst[kk + 2][lid] = w4.z; Wst[kk + 3][lid] = w4.w;
        }
        __syncthreads();
        #pragma unroll
        for (int k = 0; k < 32; k++) {
            const float4 a0 = *(const float4*)&Ast[k][ty * 8];
            const float4 a1 = *(const float4*)&Ast[k][ty * 8 + 4];
            const float4 b0 = *(const float4*)&Wst[k][tx * 8];
            const float4 b1 = *(const float4*)&Wst[k][tx * 8 + 4];
            const float av[8] = {a0.x, a0.y, a0.z, a0.w, a1.x, a1.y, a1.z, a1.w};
            const float bv2[8] = {b0.x, b0.y, b0.z, b0.w, b1.x, b1.y, b1.z, b1.w};
            #pragma unroll
            for (int i = 0; i < 8; i++)
                #pragma unroll
                for (int j = 0; j < 8; j++)
                    acc[i][j] += av[i] * bv2[j];
        }
        __syncthreads();
    }

    #pragma unroll
    for (int j = 0; j < 8; j++) {
        const int f = tx * 8 + j;
        const int p = (f & 3) * 32 + (f >> 2);   // head-major permute
        const float bb = bias[f];
        #pragma unroll
        for (int i = 0; i < 8; i++) {
            const int m = m0 + ty * 8 + i;
            if (m < Nn)
                out[(size_t)m * 128 + p] = (acc[i][j] + bb) * alpha;
        }
    }
}

// ---------------------------------------------------------------------------
// Fused edge attention: one warp per destination node.
// row is sorted -> binary-search edge range. Online softmax per head.
// Lane layout: head h = lane>>3, each lane owns 4 dims (lane*4 == h*32 + sub*4).
// ---------------------------------------------------------------------------
__global__ __launch_bounds__(256) void edge_attn(
    const int* __restrict__ row, const int* __restrict__ col, int E, int Nn)
{
    const int warp = (blockIdx.x * blockDim.x + threadIdx.x) >> 5;
    const int lane = threadIdx.x & 31;
    if (warp >= Nn) return;
    const int i = warp;

    // edge range [start, end) via two binary searches on sorted row
    int lo = 0, hi = E;
    while (lo < hi) { int mid = (lo + hi) >> 1; if (row[mid] < i) lo = mid + 1; else hi = mid; }
    const int start = lo;
    hi = E;
    while (lo < hi) { int mid = (lo + hi) >> 1; if (row[mid] < i + 1) lo = mid + 1; else hi = mid; }
    const int end = lo;

    const float4 qv = *(const float4*)&g_Q[(size_t)i * 128 + lane * 4];

    float m = -3.0e38f, l = 0.f;
    float4 acc = make_float4(0.f, 0.f, 0.f, 0.f);

    for (int e = start; e < end; e++) {
        const int c = col[e];
        const float4 kv = *(const float4*)&g_K[(size_t)c * 128 + lane * 4];
        float s = qv.x * kv.x + qv.y * kv.y + qv.z * kv.z + qv.w * kv.w;
        // reduce across the 8 lanes of this head
        s += __shfl_xor_sync(0xffffffffu, s, 1);
        s += __shfl_xor_sync(0xffffffffu, s, 2);
        s += __shfl_xor_sync(0xffffffffu, s, 4);

        const float mn = fmaxf(m, s);
        const float sc = __expf(m - mn);   // exp(-inf) == 0 on first edge
        const float p  = __expf(s - mn);
        l = l * sc + p;
        m = mn;

        const float4 vv = *(const float4*)&g_V[(size_t)c * 128 + lane * 4];
        acc.x = acc.x * sc + p * vv.x;
        acc.y = acc.y * sc + p * vv.y;
        acc.z = acc.z * sc + p * vv.z;
        acc.w = acc.w * sc + p * vv.w;
    }

    const float inv = (l > 0.f) ? (1.f / l) : 0.f;  // degree-0 node -> y = 0
    float4 o;
    o.x = acc.x * inv; o.y = acc.y * inv; o.z = acc.z * inv; o.w = acc.w * inv;
    *(float4*)&g_Y[(size_t)i * 128 + lane * 4] = o;
}

// ---------------------------------------------------------------------------
// Output projection: out[n][o] = sum_g Y[n][g] * Wo[o][invperm(g)] + bo[o]
// invperm(g) = (g&31)*4 + (g>>5) undoes the head-major storage of Y.
// ---------------------------------------------------------------------------
__global__ __launch_bounds__(256) void out_gemm(
    const float* __restrict__ Wo, const float* __restrict__ bo,
    float* __restrict__ out, int Nn)
{
    __shared__ float Ast[32][128];
    __shared__ float Wst[32][128];

    const int m0  = blockIdx.x * 128;
    const int tid = threadIdx.x;
    const int tx  = tid & 15;
    const int ty  = tid >> 4;
    const int lid = tid & 127;
    const int kq  = (tid >> 7) * 16;

    float acc[8][8];
    #pragma unroll
    for (int i = 0; i < 8; i++)
        #pragma unroll
        for (int j = 0; j < 8; j++) acc[i][j] = 0.f;

    for (int k0 = 0; k0 < 128; k0 += 32) {
        #pragma unroll
        for (int it = 0; it < 4; it++) {
            const int kk = kq + it * 4;
            float4 a4 = make_float4(0.f, 0.f, 0.f, 0.f);
            if (m0 + lid < Nn)
                a4 = *(const float4*)&g_Y[(size_t)(m0 + lid) * 128 + k0 + kk];
            Ast[kk + 0][lid] = a4.x; Ast[kk + 1][lid] = a4.y;
            Ast[kk + 2][lid] = a4.z; Ast[kk + 3][lid] = a4.w;
            #pragma unroll
            for (int s = 0; s < 4; s++) {
                const int g = k0 + kk + s;
                const int f = (g & 31) * 4 + (g >> 5);   // inverse head permute
                Wst[kk + s][lid] = Wo[(size_t)lid * 128 + f];
            }
        }
        __syncthreads();
        #pragma unroll
        for (int k = 0; k < 32; k++) {
            const float4 a0 = *(const float4*)&Ast[k][ty * 8];
            const float4 a1 = *(const float4*)&Ast[k][ty * 8 + 4];
            const float4 b0 = *(const float4*)&Wst[k][tx * 8];
            const float4 b1 = *(const float4*)&Wst[k][tx * 8 + 4];
            const float av[8] = {a0.x, a0.y, a0.z, a0.w, a1.x, a1.y, a1.z, a1.w};
            const float bv2[8] = {b0.x, b0.y, b0.z, b0.w, b1.x, b1.y, b1.z, b1.w};
            #pragma unroll
            for (int i = 0; i < 8; i++)
                #pragma unroll
                for (int j = 0; j < 8; j++)
                    acc[i][j] += av[i] * bv2[j];
        }
        __syncthreads();
    }

    #pragma unroll
    for (int j = 0; j < 8; j++) {
        const int f = tx * 8 + j;
        const float bb = bo[f];
        #pragma unroll
        for (int i = 0; i < 8; i++) {
            const int m = m0 + ty * 8 + i;
            if (m < Nn)
                out[(size_t)m * 128 + f] = acc[i][j] + bb;
        }
    }
}

// ---------------------------------------------------------------------------
extern "C" void kernel_launch(void* const* d_in, const int* in_sizes, int n_in,
                              void* d_out, int out_size)
{
    const float* x  = (const float*)d_in[0];
    const int*   row = (const int*)d_in[1];
    const int*   col = (const int*)d_in[2];
    const float* Wq = (const float*)d_in[3];
    const float* bq = (const float*)d_in[4];
    const float* Wk = (const float*)d_in[5];
    const float* bk = (const float*)d_in[6];
    const float* Wv = (const float*)d_in[7];
    const float* bv = (const float*)d_in[8];
    const float* Wo = (const float*)d_in[9];
    const float* bo = (const float*)d_in[10];

    const int Nn = in_sizes[0] / 128;
    const int E  = in_sizes[1];

    dim3 gQKV((Nn + 127) / 128, 3);
    qkv_gemm<<<gQKV, 256>>>(x, Wq, bq, Wk, bk, Wv, bv, Nn);

    const int edge_blocks = (Nn * 32 + 255) / 256;
    edge_attn<<<edge_blocks, 256>>>(row, col, E, Nn);

    dim3 gO((Nn + 127) / 128, 1);
    out_gemm<<<gO, 256>>>(Wo, bo, (float*)d_out, Nn);
}

// round 3
// speedup vs baseline: 1.2113x; 1.2113x over previous
#include <cuda_runtime.h>
#include <cuda_bf16.h>
#include <cstdint>

// Problem constants: N=100000, E=800000, D=128, H=4, DH=32
#define MAX_N 100096
#define ND ((size_t)MAX_N * 128)

__device__ float g_Q[ND];
__device__ float g_K[ND];
__device__ float g_V[ND];
__device__ float g_Y[ND];

#define LDROW 72   // bf16 elems per smem row: 64 data + 8 pad (144B, 16B aligned, conflict-free ldmatrix)
#define TILE_ELEMS (128 * LDROW)
#define SM_TOTAL (4 * TILE_ELEMS * 2)   // Ahi, Alo, Bhi, Blo = 73728 B

// ---------------------------------------------------------------------------
__device__ __forceinline__ uint32_t smem_u32(const void* p) {
    uint32_t a;
    asm("{ .reg .u64 t; cvta.to.shared.u64 t, %1; cvt.u32.u64 %0, t; }" : "=r"(a) : "l"(p));
    return a;
}
__device__ __forceinline__ void ldm_x4(uint32_t* r, uint32_t addr) {
    asm volatile("ldmatrix.sync.aligned.m8n8.x4.shared.b16 {%0,%1,%2,%3}, [%4];"
                 : "=r"(r[0]), "=r"(r[1]), "=r"(r[2]), "=r"(r[3]) : "r"(addr));
}
__device__ __forceinline__ void mma16816(float* d, const uint32_t* a, const uint32_t* b) {
    asm volatile(
        "mma.sync.aligned.m16n8k16.row.col.f32.bf16.bf16.f32 "
        "{%0,%1,%2,%3},{%4,%5,%6,%7},{%8,%9},{%0,%1,%2,%3};"
        : "+f"(d[0]), "+f"(d[1]), "+f"(d[2]), "+f"(d[3])
        : "r"(a[0]), "r"(a[1]), "r"(a[2]), "r"(a[3]), "r"(b[0]), "r"(b[1]));
}

// split one float4 into hi/lo bf16 pairs and store 8 bytes to each buffer
__device__ __forceinline__ void split_store4(__nv_bfloat16* hi, __nv_bfloat16* lo, float4 v) {
    __nv_bfloat16 h0 = __float2bfloat16_rn(v.x), h1 = __float2bfloat16_rn(v.y);
    __nv_bfloat16 h2 = __float2bfloat16_rn(v.z), h3 = __float2bfloat16_rn(v.w);
    __nv_bfloat162 hp0; hp0.x = h0; hp0.y = h1;
    __nv_bfloat162 hp1; hp1.x = h2; hp1.y = h3;
    __nv_bfloat162 lp0, lp1;
    lp0.x = __float2bfloat16_rn(v.x - __bfloat162float(h0));
    lp0.y = __float2bfloat16_rn(v.y - __bfloat162float(h1));
    lp1.x = __float2bfloat16_rn(v.z - __bfloat162float(h2));
    lp1.y = __float2bfloat16_rn(v.w - __bfloat162float(h3));
    *reinterpret_cast<__nv_bfloat162*>(hi)     = hp0;
    *reinterpret_cast<__nv_bfloat162*>(hi + 2) = hp1;
    *reinterpret_cast<__nv_bfloat162*>(lo)     = lp0;
    *reinterpret_cast<__nv_bfloat162*>(lo + 2) = lp1;
}

// ---------------------------------------------------------------------------
// Core MMA tile compute: acc += Ahi*Bhi + Ahi*Blo + Alo*Bhi over this 64-K chunk.
// Warp tile 32x64: warp_m in 0..3, warp_n in 0..1.
// ---------------------------------------------------------------------------
__device__ __forceinline__ void mma_chunk(
    float acc[2][8][4], uint32_t sbase, int warp_m, int warp_n, int lane)
{
    const uint32_t AHI = sbase;
    const uint32_t ALO = sbase + TILE_ELEMS * 2;
    const uint32_t BHI = sbase + 2 * TILE_ELEMS * 2;
    const uint32_t BLO = sbase + 3 * TILE_ELEMS * 2;

    // A lane addressing: row=(l&15)+mi*16+warp_m*32, koff=((l>>4)<<3)
    const uint32_t a_off = (uint32_t)((warp_m * 32 + (lane & 15)) * LDROW + ((lane >> 4) << 3)) * 2;
    // B lane addressing: n_row=(l&7)+((l>>4)<<3)+nb2*16+warp_n*64, koff=(l&8)
    const uint32_t b_off = (uint32_t)((warp_n * 64 + (lane & 7) + ((lane >> 4) << 3)) * LDROW +
                                      (lane & 8)) * 2;

    #pragma unroll
    for (int ks = 0; ks < 4; ks++) {
        const uint32_t kb = (uint32_t)(ks * 16) * 2;
        uint32_t aH[2][4], aL[2][4], bH[4][4], bL[4][4];
        #pragma unroll
        for (int mi = 0; mi < 2; mi++)
            ldm_x4(aH[mi], AHI + a_off + kb + (uint32_t)(mi * 16 * LDROW) * 2);
        #pragma unroll
        for (int g = 0; g < 4; g++)
            ldm_x4(bH[g], BHI + b_off + kb + (uint32_t)(g * 16 * LDROW) * 2);
        // Ahi x Bhi
        #pragma unroll
        for (int mi = 0; mi < 2; mi++)
            #pragma unroll
            for (int g = 0; g < 4; g++) {
                mma16816(acc[mi][2 * g],     aH[mi], bH[g]);
                mma16816(acc[mi][2 * g + 1], aH[mi], bH[g] + 2);
            }
        // Alo x Bhi
        #pragma unroll
        for (int mi = 0; mi < 2; mi++)
            ldm_x4(aL[mi], ALO + a_off + kb + (uint32_t)(mi * 16 * LDROW) * 2);
        #pragma unroll
        for (int mi = 0; mi < 2; mi++)
            #pragma unroll
            for (int g = 0; g < 4; g++) {
                mma16816(acc[mi][2 * g],     aL[mi], bH[g]);
                mma16816(acc[mi][2 * g + 1], aL[mi], bH[g] + 2);
            }
        // Ahi x Blo
        #pragma unroll
        for (int g = 0; g < 4; g++)
            ldm_x4(bL[g], BLO + b_off + kb + (uint32_t)(g * 16 * LDROW) * 2);
        #pragma unroll
        for (int mi = 0; mi < 2; mi++)
            #pragma unroll
            for (int g = 0; g < 4; g++) {
                mma16816(acc[mi][2 * g],     aH[mi], bL[g]);
                mma16816(acc[mi][2 * g + 1], aH[mi], bL[g] + 2);
            }
    }
}

// ---------------------------------------------------------------------------
// QKV projection: per CTA one 128-row tile of x; 3 GEMMs (Q,K,V).
// Output head-major permuted: feature f -> (f&3)*32 + (f>>2); Q scaled 0.5.
// ---------------------------------------------------------------------------
__global__ __launch_bounds__(256) void qkv_tc(
    const float* __restrict__ x,
    const float* __restrict__ Wq, const float* __restrict__ bq,
    const float* __restrict__ Wk, const float* __restrict__ bk,
    const float* __restrict__ Wv, const float* __restrict__ bv,
    int Nn)
{
    extern __shared__ __nv_bfloat16 sm[];
    __nv_bfloat16* Ahi = sm;
    __nv_bfloat16* Alo = sm + TILE_ELEMS;
    __nv_bfloat16* Bhi = sm + 2 * TILE_ELEMS;
    __nv_bfloat16* Blo = sm + 3 * TILE_ELEMS;
    const uint32_t sbase = smem_u32(sm);

    const int tid = threadIdx.x;
    const int lane = tid & 31;
    const int w = tid >> 5;
    const int warp_m = w >> 1;
    const int warp_n = w & 1;
    const int m0 = blockIdx.x * 128;

    const int lr = tid >> 1;            // loader row 0..127
    const int lc = (tid & 1) * 32;      // loader col base

    const float* Ws[3] = {Wq, Wk, Wv};
    const float* Bs[3] = {bq, bk, bv};

    for (int o = 0; o < 3; o++) {
        float acc[2][8][4];
        #pragma unroll
        for (int mi = 0; mi < 2; mi++)
            #pragma unroll
            for (int nb = 0; nb < 8; nb++)
                #pragma unroll
                for (int j = 0; j < 4; j++) acc[mi][nb][j] = 0.f;

        for (int chunk = 0; chunk < 2; chunk++) {
            // load A (x tile) and B (weight tile), split hi/lo
            const bool valid = (m0 + lr) < Nn;
            const float* xr = x + (size_t)(m0 + lr) * 128 + chunk * 64;
            const float* wr = Ws[o] + (size_t)lr * 128 + chunk * 64;
            #pragma unroll
            for (int i = 0; i < 8; i++) {
                const int c = lc + i * 4;
                float4 va = valid ? *(const float4*)(xr + c) : make_float4(0.f, 0.f, 0.f, 0.f);
                split_store4(&Ahi[lr * LDROW + c], &Alo[lr * LDROW + c], va);
                float4 vb = *(const float4*)(wr + c);
                split_store4(&Bhi[lr * LDROW + c], &Blo[lr * LDROW + c], vb);
            }
            __syncthreads();
            mma_chunk(acc, sbase, warp_m, warp_n, lane);
            __syncthreads();
        }

        // epilogue: head-major permuted store
        float* dst = (o == 0) ? g_Q : (o == 1) ? g_K : g_V;
        const float alpha = (o == 0) ? 0.5f : 1.0f;
        const float* bias = Bs[o];
        #pragma unroll
        for (int mi = 0; mi < 2; mi++) {
            const int mrow = m0 + warp_m * 32 + mi * 16 + (lane >> 2);
            #pragma unroll
            for (int nb = 0; nb < 8; nb++) {
                const int f0 = warp_n * 64 + nb * 8 + (lane & 3) * 2;
                const int f1 = f0 + 1;
                const int p0 = (f0 & 3) * 32 + (f0 >> 2);
                const int p1 = (f1 & 3) * 32 + (f1 >> 2);
                const float b0 = __ldg(&bias[f0]);
                const float b1 = __ldg(&bias[f1]);
                if (mrow < Nn) {
                    dst[(size_t)mrow * 128 + p0] = (acc[mi][nb][0] + b0) * alpha;
                    dst[(size_t)mrow * 128 + p1] = (acc[mi][nb][1] + b1) * alpha;
                }
                if (mrow + 8 < Nn) {
                    dst[(size_t)(mrow + 8) * 128 + p0] = (acc[mi][nb][2] + b0) * alpha;
                    dst[(size_t)(mrow + 8) * 128 + p1] = (acc[mi][nb][3] + b1) * alpha;
                }
            }
        }
        __syncthreads();   // protect smem before next o reload
    }
}

// ---------------------------------------------------------------------------
// Output projection: A = g_Y (head-major), B = Wo with K-dim inverse permute.
// ---------------------------------------------------------------------------
__global__ __launch_bounds__(256) void out_tc(
    const float* __restrict__ Wo, const float* __restrict__ bo,
    float* __restrict__ out, int Nn)
{
    extern __shared__ __nv_bfloat16 sm[];
    __nv_bfloat16* Ahi = sm;
    __nv_bfloat16* Alo = sm + TILE_ELEMS;
    __nv_bfloat16* Bhi = sm + 2 * TILE_ELEMS;
    __nv_bfloat16* Blo = sm + 3 * TILE_ELEMS;
    const uint32_t sbase = smem_u32(sm);

    const int tid = threadIdx.x;
    const int lane = tid & 31;
    const int w = tid >> 5;
    const int warp_m = w >> 1;
    const int warp_n = w & 1;
    const int m0 = blockIdx.x * 128;

    const int lr = tid >> 1;
    const int lc = (tid & 1) * 32;

    float acc[2][8][4];
    #pragma unroll
    for (int mi = 0; mi < 2; mi++)
        #pragma unroll
        for (int nb = 0; nb < 8; nb++)
            #pragma unroll
            for (int j = 0; j < 4; j++) acc[mi][nb][j] = 0.f;

    for (int chunk = 0; chunk < 2; chunk++) {
        const bool valid = (m0 + lr) < Nn;
        const float* yr = g_Y + (size_t)(m0 + lr) * 128 + chunk * 64;
        const float* wr = Wo + (size_t)lr * 128;
        #pragma unroll
        for (int i = 0; i < 8; i++) {
            const int c = lc + i * 4;
            float4 va = valid ? *(const float4*)(yr + c) : make_float4(0.f, 0.f, 0.f, 0.f);
            split_store4(&Ahi[lr * LDROW + c], &Alo[lr * LDROW + c], va);
            // B with inverse head permute on the K dimension
            float4 vb;
            {
                const int g0 = chunk * 64 + c;
                vb.x = wr[((g0 + 0) & 31) * 4 + ((g0 + 0) >> 5)];
                vb.y = wr[((g0 + 1) & 31) * 4 + ((g0 + 1) >> 5)];
                vb.z = wr[((g0 + 2) & 31) * 4 + ((g0 + 2) >> 5)];
                vb.w = wr[((g0 + 3) & 31) * 4 + ((g0 + 3) >> 5)];
            }
            split_store4(&Bhi[lr * LDROW + c], &Blo[lr * LDROW + c], vb);
        }
        __syncthreads();
        mma_chunk(acc, sbase, warp_m, warp_n, lane);
        __syncthreads();
    }

    #pragma unroll
    for (int mi = 0; mi < 2; mi++) {
        const int mrow = m0 + warp_m * 32 + mi * 16 + (lane >> 2);
        #pragma unroll
        for (int nb = 0; nb < 8; nb++) {
            const int f0 = warp_n * 64 + nb * 8 + (lane & 3) * 2;
            const float b0 = __ldg(&bo[f0]);
            const float b1 = __ldg(&bo[f0 + 1]);
            if (mrow < Nn) {
                float2 v = make_float2(acc[mi][nb][0] + b0, acc[mi][nb][1] + b1);
                *(float2*)&out[(size_t)mrow * 128 + f0] = v;
            }
            if (mrow + 8 < Nn) {
                float2 v = make_float2(acc[mi][nb][2] + b0, acc[mi][nb][3] + b1);
                *(float2*)&out[(size_t)(mrow + 8) * 128 + f0] = v;
            }
        }
    }
}

// ---------------------------------------------------------------------------
// Fused edge attention: one warp per destination node (unchanged from R1).
// ---------------------------------------------------------------------------
__global__ __launch_bounds__(256) void edge_attn(
    const int* __restrict__ row, const int* __restrict__ col, int E, int Nn)
{
    const int warp = (blockIdx.x * blockDim.x + threadIdx.x) >> 5;
    const int lane = threadIdx.x & 31;
    if (warp >= Nn) return;
    const int i = warp;

    int lo = 0, hi = E;
    while (lo < hi) { int mid = (lo + hi) >> 1; if (row[mid] < i) lo = mid + 1; else hi = mid; }
    const int start = lo;
    hi = E;
    while (lo < hi) { int mid = (lo + hi) >> 1; if (row[mid] < i + 1) lo = mid + 1; else hi = mid; }
    const int end = lo;

    const float4 qv = *(const float4*)&g_Q[(size_t)i * 128 + lane * 4];

    float m = -3.0e38f, l = 0.f;
    float4 acc = make_float4(0.f, 0.f, 0.f, 0.f);

    for (int e = start; e < end; e++) {
        const int c = col[e];
        const float4 kv = *(const float4*)&g_K[(size_t)c * 128 + lane * 4];
        float s = qv.x * kv.x + qv.y * kv.y + qv.z * kv.z + qv.w * kv.w;
        s += __shfl_xor_sync(0xffffffffu, s, 1);
        s += __shfl_xor_sync(0xffffffffu, s, 2);
        s += __shfl_xor_sync(0xffffffffu, s, 4);

        const float mn = fmaxf(m, s);
        const float sc = __expf(m - mn);
        const float p  = __expf(s - mn);
        l = l * sc + p;
        m = mn;

        const float4 vv = *(const float4*)&g_V[(size_t)c * 128 + lane * 4];
        acc.x = acc.x * sc + p * vv.x;
        acc.y = acc.y * sc + p * vv.y;
        acc.z = acc.z * sc + p * vv.z;
        acc.w = acc.w * sc + p * vv.w;
    }

    const float inv = (l > 0.f) ? (1.f / l) : 0.f;
    float4 o;
    o.x = acc.x * inv; o.y = acc.y * inv; o.z = acc.z * inv; o.w = acc.w * inv;
    *(float4*)&g_Y[(size_t)i * 128 + lane * 4] = o;
}

// ---------------------------------------------------------------------------
extern "C" void kernel_launch(void* const* d_in, const int* in_sizes, int n_in,
                              void* d_out, int out_size)
{
    const float* x  = (const float*)d_in[0];
    const int*   row = (const int*)d_in[1];
    const int*   col = (const int*)d_in[2];
    const float* Wq = (const float*)d_in[3];
    const float* bq = (const float*)d_in[4];
    const float* Wk = (const float*)d_in[5];
    const float* bk = (const float*)d_in[6];
    const float* Wv = (const float*)d_in[7];
    const float* bv = (const float*)d_in[8];
    const float* Wo = (const float*)d_in[9];
    const float* bo = (const float*)d_in[10];

    const int Nn = in_sizes[0] / 128;
    const int E  = in_sizes[1];
    const int tiles = (Nn + 127) / 128;

    cudaFuncSetAttribute(qkv_tc, cudaFuncAttributeMaxDynamicSharedMemorySize, SM_TOTAL);
    cudaFuncSetAttribute(out_tc, cudaFuncAttributeMaxDynamicSharedMemorySize, SM_TOTAL);

    qkv_tc<<<tiles, 256, SM_TOTAL>>>(x, Wq, bq, Wk, bk, Wv, bv, Nn);

    const int edge_blocks = (Nn * 32 + 255) / 256;
    edge_attn<<<edge_blocks, 256>>>(row, col, E, Nn);

    out_tc<<<tiles, 256, SM_TOTAL>>>(Wo, bo, (float*)d_out, Nn);
}

// round 4
// speedup vs baseline: 1.5251x; 1.2590x over previous
#include <cuda_runtime.h>
#include <cuda_bf16.h>
#include <cstdint>

// Problem constants: N=100000, E=800000, D=128, H=4, DH=32
#define MAX_N 100096
#define ND ((size_t)MAX_N * 128)

__device__ float g_Q[ND];
__device__ float g_K[ND];
__device__ float g_V[ND];
__device__ __nv_bfloat16 g_Xhi[ND], g_Xlo[ND];
__device__ __nv_bfloat16 g_Yhi[ND], g_Ylo[ND];
__device__ __nv_bfloat16 g_Whi[4 * 16384], g_Wlo[4 * 16384];  // Wq,Wk,Wv,Wo(K-permuted)

// smem tile: rows of 128 bf16 + 8 pad (136 elems = 272B -> conflict-free ldmatrix)
#define LDROW 136
#define AHI_E 0
#define ALO_E (64 * LDROW)
#define BHI_E (2 * 64 * LDROW)
#define BLO_E (2 * 64 * LDROW + 128 * LDROW)
#define SMEM_ELEMS (2 * 64 * LDROW + 2 * 128 * LDROW)
#define SMEM_BYTES (SMEM_ELEMS * 2)   // 104448

// ---------------------------------------------------------------------------
__device__ __forceinline__ uint32_t smem_u32(const void* p) {
    uint32_t a;
    asm("{ .reg .u64 t; cvta.to.shared.u64 t, %1; cvt.u32.u64 %0, t; }" : "=r"(a) : "l"(p));
    return a;
}
__device__ __forceinline__ void ldm_x4(uint32_t* r, uint32_t addr) {
    asm volatile("ldmatrix.sync.aligned.m8n8.x4.shared.b16 {%0,%1,%2,%3}, [%4];"
                 : "=r"(r[0]), "=r"(r[1]), "=r"(r[2]), "=r"(r[3]) : "r"(addr));
}
__device__ __forceinline__ void mma16816(float* d, const uint32_t* a, const uint32_t* b) {
    asm volatile(
        "mma.sync.aligned.m16n8k16.row.col.f32.bf16.bf16.f32 "
        "{%0,%1,%2,%3},{%4,%5,%6,%7},{%8,%9},{%0,%1,%2,%3};"
        : "+f"(d[0]), "+f"(d[1]), "+f"(d[2]), "+f"(d[3])
        : "r"(a[0]), "r"(a[1]), "r"(a[2]), "r"(a[3]), "r"(b[0]), "r"(b[1]));
}
__device__ __forceinline__ void cp16(uint32_t saddr, const void* gptr) {
    asm volatile("cp.async.ca.shared.global [%0], [%1], 16;" :: "r"(saddr), "l"(gptr));
}
#define CP_WAIT_ALL() \
    asm volatile("cp.async.commit_group;\ncp.async.wait_group 0;" ::: "memory")

// ---------------------------------------------------------------------------
// One-shot conversion: x -> g_Xhi/lo ; {Wq,Wk,Wv,Wo(K-perm)} -> g_Whi/lo
// ---------------------------------------------------------------------------
__global__ void convert_all(const float* __restrict__ x,
                            const float* __restrict__ Wq, const float* __restrict__ Wk,
                            const float* __restrict__ Wv, const float* __restrict__ Wo,
                            int Nn)
{
    const int idx = blockIdx.x * blockDim.x + threadIdx.x;
    if (blockIdx.y == 0) {
        const int total = Nn * 32;                 // float4s in x
        if (idx < total) {
            float4 v = ((const float4*)x)[idx];
            __nv_bfloat16 h0 = __float2bfloat16_rn(v.x), h1 = __float2bfloat16_rn(v.y);
            __nv_bfloat16 h2 = __float2bfloat16_rn(v.z), h3 = __float2bfloat16_rn(v.w);
            __nv_bfloat162 hp0, hp1, lp0, lp1;
            hp0.x = h0; hp0.y = h1; hp1.x = h2; hp1.y = h3;
            lp0.x = __float2bfloat16_rn(v.x - __bfloat162float(h0));
            lp0.y = __float2bfloat16_rn(v.y - __bfloat162float(h1));
            lp1.x = __float2bfloat16_rn(v.z - __bfloat162float(h2));
            lp1.y = __float2bfloat16_rn(v.w - __bfloat162float(h3));
            *(__nv_bfloat162*)&g_Xhi[idx * 4]     = hp0;
            *(__nv_bfloat162*)&g_Xhi[idx * 4 + 2] = hp1;
            *(__nv_bfloat162*)&g_Xlo[idx * 4]     = lp0;
            *(__nv_bfloat162*)&g_Xlo[idx * 4 + 2] = lp1;
        }
    } else {
        if (idx < 4 * 16384) {
            const int mat = idx >> 14, e = idx & 16383;
            const int f = e >> 7, k = e & 127;
            const float* W = (mat == 0) ? Wq : (mat == 1) ? Wk : (mat == 2) ? Wv : Wo;
            const int kk = (mat == 3) ? ((k & 31) * 4 + (k >> 5)) : k;  // undo head-major for Wo
            const float v = W[f * 128 + kk];
            __nv_bfloat16 h = __float2bfloat16_rn(v);
            g_Whi[idx] = h;
            g_Wlo[idx] = __float2bfloat16_rn(v - __bfloat162float(h));
        }
    }
}

// ---------------------------------------------------------------------------
// Core: acc += Ahi*Bhi + Alo*Bhi + Ahi*Blo over K=128 (resident in smem).
// Tile M=64 x N=128; 8 warps; warp tile 32x32 (warp_m=w&1, warp_n=w>>1).
// ---------------------------------------------------------------------------
__device__ __forceinline__ void mma_all(float acc[2][4][4], uint32_t sbase,
                                        int warp_m, int warp_n, int lane)
{
    const uint32_t AHI = sbase + AHI_E * 2;
    const uint32_t ALO = sbase + ALO_E * 2;
    const uint32_t BHI = sbase + BHI_E * 2;
    const uint32_t BLO = sbase + BLO_E * 2;
    const uint32_t a_off = (uint32_t)((warp_m * 32 + (lane & 15)) * LDROW + ((lane >> 4) << 3)) * 2;
    const uint32_t b_off = (uint32_t)((warp_n * 32 + (lane & 7) + ((lane >> 4) << 3)) * LDROW +
                                      (lane & 8)) * 2;
    #pragma unroll
    for (int ks = 0; ks < 8; ks++) {
        const uint32_t kb = (uint32_t)ks * 32;   // 16 bf16 = 32 B per k-step
        uint32_t aH[2][4], aL[2][4], bH[2][4], bL[2][4];
        #pragma unroll
        for (int mi = 0; mi < 2; mi++)
            ldm_x4(aH[mi], AHI + a_off + kb + (uint32_t)(mi * 16 * LDROW) * 2);
        #pragma unroll
        for (int g = 0; g < 2; g++)
            ldm_x4(bH[g], BHI + b_off + kb + (uint32_t)(g * 16 * LDROW) * 2);
        #pragma unroll
        for (int mi = 0; mi < 2; mi++)
            #pragma unroll
            for (int g = 0; g < 2; g++) {
                mma16816(acc[mi][2 * g],     aH[mi], bH[g]);
                mma16816(acc[mi][2 * g + 1], aH[mi], bH[g] + 2);
            }
        #pragma unroll
        for (int mi = 0; mi < 2; mi++)
            ldm_x4(aL[mi], ALO + a_off + kb + (uint32_t)(mi * 16 * LDROW) * 2);
        #pragma unroll
        for (int mi = 0; mi < 2; mi++)
            #pragma unroll
            for (int g = 0; g < 2; g++) {
                mma16816(acc[mi][2 * g],     aL[mi], bH[g]);
                mma16816(acc[mi][2 * g + 1], aL[mi], bH[g] + 2);
            }
        #pragma unroll
        for (int g = 0; g < 2; g++)
            ldm_x4(bL[g], BLO + b_off + kb + (uint32_t)(g * 16 * LDROW) * 2);
        #pragma unroll
        for (int mi = 0; mi < 2; mi++)
            #pragma unroll
            for (int g = 0; g < 2; g++) {
                mma16816(acc[mi][2 * g],     aH[mi], bL[g]);
                mma16816(acc[mi][2 * g + 1], aH[mi], bL[g] + 2);
            }
    }
}

// async-load one GEMM tile pair: A (64x128 hi/lo from Asrc) + B (128x128 hi/lo from Bsrc)
__device__ __forceinline__ void load_tiles(uint32_t sbase, int tid,
                                           const __nv_bfloat16* Ahi, const __nv_bfloat16* Alo,
                                           const __nv_bfloat16* Bhi, const __nv_bfloat16* Blo)
{
    #pragma unroll
    for (int c = 0; c < 1024; c += 256) {
        const int cc = c + tid;
        const int r = cc >> 4, col = (cc & 15) * 8;
        cp16(sbase + (uint32_t)(AHI_E + r * LDROW + col) * 2, Ahi + r * 128 + col);
        cp16(sbase + (uint32_t)(ALO_E + r * LDROW + col) * 2, Alo + r * 128 + col);
    }
    #pragma unroll
    for (int c = 0; c < 2048; c += 256) {
        const int cc = c + tid;
        const int r = cc >> 4, col = (cc & 15) * 8;
        cp16(sbase + (uint32_t)(BHI_E + r * LDROW + col) * 2, Bhi + r * 128 + col);
        cp16(sbase + (uint32_t)(BLO_E + r * LDROW + col) * 2, Blo + r * 128 + col);
    }
    CP_WAIT_ALL();
}

// ---------------------------------------------------------------------------
// QKV projection: grid = (M-tiles, 3). Head-major permuted outputs; Q * 0.5.
// ---------------------------------------------------------------------------
__global__ __launch_bounds__(256, 2) void qkv_tc(
    const float* __restrict__ bq, const float* __restrict__ bk,
    const float* __restrict__ bv, int Nn)
{
    extern __shared__ __nv_bfloat16 sm[];
    const uint32_t sbase = smem_u32(sm);
    const int tid = threadIdx.x;
    const int lane = tid & 31;
    const int w = tid >> 5;
    const int warp_m = w & 1;
    const int warp_n = w >> 1;
    const int m0 = blockIdx.x * 64;
    const int o = blockIdx.y;

    load_tiles(sbase, tid,
               g_Xhi + (size_t)m0 * 128, g_Xlo + (size_t)m0 * 128,
               g_Whi + o * 16384, g_Wlo + o * 16384);
    __syncthreads();

    float acc[2][4][4];
    #pragma unroll
    for (int mi = 0; mi < 2; mi++)
        #pragma unroll
        for (int nb = 0; nb < 4; nb++)
            #pragma unroll
            for (int j = 0; j < 4; j++) acc[mi][nb][j] = 0.f;

    mma_all(acc, sbase, warp_m, warp_n, lane);

    float* dst = (o == 0) ? g_Q : (o == 1) ? g_K : g_V;
    const float alpha = (o == 0) ? 0.5f : 1.0f;
    const float* bias = (o == 0) ? bq : (o == 1) ? bk : bv;

    #pragma unroll
    for (int mi = 0; mi < 2; mi++) {
        const int mrow = m0 + warp_m * 32 + mi * 16 + (lane >> 2);
        #pragma unroll
        for (int nb = 0; nb < 4; nb++) {
            const int f0 = warp_n * 32 + nb * 8 + (lane & 3) * 2;
            const int f1 = f0 + 1;
            const int p0 = (f0 & 3) * 32 + (f0 >> 2);
            const int p1 = (f1 & 3) * 32 + (f1 >> 2);
            const float b0 = __ldg(&bias[f0]);
            const float b1 = __ldg(&bias[f1]);
            if (mrow < Nn) {
                dst[(size_t)mrow * 128 + p0] = (acc[mi][nb][0] + b0) * alpha;
                dst[(size_t)mrow * 128 + p1] = (acc[mi][nb][1] + b1) * alpha;
            }
            if (mrow + 8 < Nn) {
                dst[(size_t)(mrow + 8) * 128 + p0] = (acc[mi][nb][2] + b0) * alpha;
                dst[(size_t)(mrow + 8) * 128 + p1] = (acc[mi][nb][3] + b1) * alpha;
            }
        }
    }
}

// ---------------------------------------------------------------------------
// Output projection: A = Y (bf16 hi/lo from edge_attn), B = Wo (pre-permuted).
// ---------------------------------------------------------------------------
__global__ __launch_bounds__(256, 2) void out_tc(
    const float* __restrict__ bo, float* __restrict__ out, int Nn)
{
    extern __shared__ __nv_bfloat16 sm[];
    const uint32_t sbase = smem_u32(sm);
    const int tid = threadIdx.x;
    const int lane = tid & 31;
    const int w = tid >> 5;
    const int warp_m = w & 1;
    const int warp_n = w >> 1;
    const int m0 = blockIdx.x * 64;

    load_tiles(sbase, tid,
               g_Yhi + (size_t)m0 * 128, g_Ylo + (size_t)m0 * 128,
               g_Whi + 3 * 16384, g_Wlo + 3 * 16384);
    __syncthreads();

    float acc[2][4][4];
    #pragma unroll
    for (int mi = 0; mi < 2; mi++)
        #pragma unroll
        for (int nb = 0; nb < 4; nb++)
            #pragma unroll
            for (int j = 0; j < 4; j++) acc[mi][nb][j] = 0.f;

    mma_all(acc, sbase, warp_m, warp_n, lane);

    #pragma unroll
    for (int mi = 0; mi < 2; mi++) {
        const int mrow = m0 + warp_m * 32 + mi * 16 + (lane >> 2);
        #pragma unroll
        for (int nb = 0; nb < 4; nb++) {
            const int f0 = warp_n * 32 + nb * 8 + (lane & 3) * 2;
            const float b0 = __ldg(&bo[f0]);
            const float b1 = __ldg(&bo[f0 + 1]);
            if (mrow < Nn) {
                float2 v = make_float2(acc[mi][nb][0] + b0, acc[mi][nb][1] + b1);
                *(float2*)&out[(size_t)mrow * 128 + f0] = v;
            }
            if (mrow + 8 < Nn) {
                float2 v = make_float2(acc[mi][nb][2] + b0, acc[mi][nb][3] + b1);
                *(float2*)&out[(size_t)(mrow + 8) * 128 + f0] = v;
            }
        }
    }
}

// ---------------------------------------------------------------------------
// Fused edge attention: one warp per destination node. Writes Y as bf16 hi/lo.
// ---------------------------------------------------------------------------
__global__ __launch_bounds__(256) void edge_attn(
    const int* __restrict__ row, const int* __restrict__ col, int E, int Nn)
{
    const int warp = (blockIdx.x * blockDim.x + threadIdx.x) >> 5;
    const int lane = threadIdx.x & 31;
    if (warp >= Nn) return;
    const int i = warp;

    int lo = 0, hi = E;
    while (lo < hi) { int mid = (lo + hi) >> 1; if (row[mid] < i) lo = mid + 1; else hi = mid; }
    const int start = lo;
    hi = E;
    while (lo < hi) { int mid = (lo + hi) >> 1; if (row[mid] < i + 1) lo = mid + 1; else hi = mid; }
    const int end = lo;

    const float4 qv = *(const float4*)&g_Q[(size_t)i * 128 + lane * 4];

    float m = -3.0e38f, l = 0.f;
    float4 acc = make_float4(0.f, 0.f, 0.f, 0.f);

    for (int e = start; e < end; e++) {
        const int c = col[e];
        const float4 kv = *(const float4*)&g_K[(size_t)c * 128 + lane * 4];
        float s = qv.x * kv.x + qv.y * kv.y + qv.z * kv.z + qv.w * kv.w;
        s += __shfl_xor_sync(0xffffffffu, s, 1);
        s += __shfl_xor_sync(0xffffffffu, s, 2);
        s += __shfl_xor_sync(0xffffffffu, s, 4);

        const float mn = fmaxf(m, s);
        const float sc = __expf(m - mn);
        const float p  = __expf(s - mn);
        l = l * sc + p;
        m = mn;

        const float4 vv = *(const float4*)&g_V[(size_t)c * 128 + lane * 4];
        acc.x = acc.x * sc + p * vv.x;
        acc.y = acc.y * sc + p * vv.y;
        acc.z = acc.z * sc + p * vv.z;
        acc.w = acc.w * sc + p * vv.w;
    }

    const float inv = (l > 0.f) ? (1.f / l) : 0.f;
    float4 o;
    o.x = acc.x * inv; o.y = acc.y * inv; o.z = acc.z * inv; o.w = acc.w * inv;

    // split-store to bf16 hi/lo
    __nv_bfloat16 h0 = __float2bfloat16_rn(o.x), h1 = __float2bfloat16_rn(o.y);
    __nv_bfloat16 h2 = __float2bfloat16_rn(o.z), h3 = __float2bfloat16_rn(o.w);
    __nv_bfloat162 hp0, hp1, lp0, lp1;
    hp0.x = h0; hp0.y = h1; hp1.x = h2; hp1.y = h3;
    lp0.x = __float2bfloat16_rn(o.x - __bfloat162float(h0));
    lp0.y = __float2bfloat16_rn(o.y - __bfloat162float(h1));
    lp1.x = __float2bfloat16_rn(o.z - __bfloat162float(h2));
    lp1.y = __float2bfloat16_rn(o.w - __bfloat162float(h3));
    const size_t base = (size_t)i * 128 + lane * 4;
    *(__nv_bfloat162*)&g_Yhi[base]     = hp0;
    *(__nv_bfloat162*)&g_Yhi[base + 2] = hp1;
    *(__nv_bfloat162*)&g_Ylo[base]     = lp0;
    *(__nv_bfloat162*)&g_Ylo[base + 2] = lp1;
}

// ---------------------------------------------------------------------------
extern "C" void kernel_launch(void* const* d_in, const int* in_sizes, int n_in,
                              void* d_out, int out_size)
{
    const float* x  = (const float*)d_in[0];
    const int*   row = (const int*)d_in[1];
    const int*   col = (const int*)d_in[2];
    const float* Wq = (const float*)d_in[3];
    const float* bq = (const float*)d_in[4];
    const float* Wk = (const float*)d_in[5];
    const float* bk = (const float*)d_in[6];
    const float* Wv = (const float*)d_in[7];
    const float* bv = (const float*)d_in[8];
    const float* Wo = (const float*)d_in[9];
    const float* bo = (const float*)d_in[10];

    const int Nn = in_sizes[0] / 128;
    const int E  = in_sizes[1];
    const int t64 = (Nn + 63) / 64;

    cudaFuncSetAttribute(qkv_tc, cudaFuncAttributeMaxDynamicSharedMemorySize, SMEM_BYTES);
    cudaFuncSetAttribute(out_tc, cudaFuncAttributeMaxDynamicSharedMemorySize, SMEM_BYTES);

    convert_all<<<dim3((Nn * 32 + 255) / 256, 2), 256>>>(x, Wq, Wk, Wv, Wo, Nn);

    qkv_tc<<<dim3(t64, 3), 256, SMEM_BYTES>>>(bq, bk, bv, Nn);

    const int edge_blocks = (Nn * 32 + 255) / 256;
    edge_attn<<<edge_blocks, 256>>>(row, col, E, Nn);

    out_tc<<<dim3(t64, 1), 256, SMEM_BYTES>>>(bo, (float*)d_out, Nn);
}

// round 5
// speedup vs baseline: 1.7868x; 1.1716x over previous
#include <cuda_runtime.h>
#include <cuda_bf16.h>
#include <cstdint>

// Problem constants: N=100000, E=800000, D=128, H=4, DH=32
#define MAX_N 100096
#define ND ((size_t)MAX_N * 128)

__device__ float g_Q[ND];
__device__ float g_K[ND];
__device__ float g_V[ND];
__device__ __nv_bfloat16 g_Xhi[ND], g_Xlo[ND];
__device__ __nv_bfloat16 g_Yhi[ND], g_Ylo[ND];
__device__ __nv_bfloat16 g_Whi[4 * 16384], g_Wlo[4 * 16384];  // Wq,Wk,Wv,Wo(K-permuted)
__device__ int g_rowptr[MAX_N + 1];

// smem tile: rows of 128 bf16 + 8 pad (136 elems = 272B -> conflict-free ldmatrix)
#define LDROW 136
#define AHI_E 0
#define ALO_E (64 * LDROW)
#define BHI_E (2 * 64 * LDROW)
#define BLO_E (2 * 64 * LDROW + 128 * LDROW)
#define SMEM_ELEMS (2 * 64 * LDROW + 2 * 128 * LDROW)
#define SMEM_BYTES (SMEM_ELEMS * 2)   // 104448

// ---------------------------------------------------------------------------
__device__ __forceinline__ uint32_t smem_u32(const void* p) {
    uint32_t a;
    asm("{ .reg .u64 t; cvta.to.shared.u64 t, %1; cvt.u32.u64 %0, t; }" : "=r"(a) : "l"(p));
    return a;
}
__device__ __forceinline__ void ldm_x4(uint32_t* r, uint32_t addr) {
    asm volatile("ldmatrix.sync.aligned.m8n8.x4.shared.b16 {%0,%1,%2,%3}, [%4];"
                 : "=r"(r[0]), "=r"(r[1]), "=r"(r[2]), "=r"(r[3]) : "r"(addr));
}
__device__ __forceinline__ void mma16816(float* d, const uint32_t* a, const uint32_t* b) {
    asm volatile(
        "mma.sync.aligned.m16n8k16.row.col.f32.bf16.bf16.f32 "
        "{%0,%1,%2,%3},{%4,%5,%6,%7},{%8,%9},{%0,%1,%2,%3};"
        : "+f"(d[0]), "+f"(d[1]), "+f"(d[2]), "+f"(d[3])
        : "r"(a[0]), "r"(a[1]), "r"(a[2]), "r"(a[3]), "r"(b[0]), "r"(b[1]));
}
__device__ __forceinline__ void cp16(uint32_t saddr, const void* gptr) {
    asm volatile("cp.async.ca.shared.global [%0], [%1], 16;" :: "r"(saddr), "l"(gptr));
}
#define CP_WAIT_ALL() \
    asm volatile("cp.async.commit_group;\ncp.async.wait_group 0;" ::: "memory")

// ---------------------------------------------------------------------------
// One-shot conversion: x -> g_Xhi/lo ; {Wq,Wk,Wv,Wo(K-perm)} -> g_Whi/lo
// ---------------------------------------------------------------------------
__global__ void convert_all(const float* __restrict__ x,
                            const float* __restrict__ Wq, const float* __restrict__ Wk,
                            const float* __restrict__ Wv, const float* __restrict__ Wo,
                            int Nn)
{
    const int idx = blockIdx.x * blockDim.x + threadIdx.x;
    if (blockIdx.y == 0) {
        const int total = Nn * 32;                 // float4s in x
        if (idx < total) {
            float4 v = ((const float4*)x)[idx];
            __nv_bfloat16 h0 = __float2bfloat16_rn(v.x), h1 = __float2bfloat16_rn(v.y);
            __nv_bfloat16 h2 = __float2bfloat16_rn(v.z), h3 = __float2bfloat16_rn(v.w);
            __nv_bfloat162 hp0, hp1, lp0, lp1;
            hp0.x = h0; hp0.y = h1; hp1.x = h2; hp1.y = h3;
            lp0.x = __float2bfloat16_rn(v.x - __bfloat162float(h0));
            lp0.y = __float2bfloat16_rn(v.y - __bfloat162float(h1));
            lp1.x = __float2bfloat16_rn(v.z - __bfloat162float(h2));
            lp1.y = __float2bfloat16_rn(v.w - __bfloat162float(h3));
            *(__nv_bfloat162*)&g_Xhi[idx * 4]     = hp0;
            *(__nv_bfloat162*)&g_Xhi[idx * 4 + 2] = hp1;
            *(__nv_bfloat162*)&g_Xlo[idx * 4]     = lp0;
            *(__nv_bfloat162*)&g_Xlo[idx * 4 + 2] = lp1;
        }
    } else {
        if (idx < 4 * 16384) {
            const int mat = idx >> 14, e = idx & 16383;
            const int f = e >> 7, k = e & 127;
            const float* W = (mat == 0) ? Wq : (mat == 1) ? Wk : (mat == 2) ? Wv : Wo;
            const int kk = (mat == 3) ? ((k & 31) * 4 + (k >> 5)) : k;  // undo head-major for Wo
            const float v = W[f * 128 + kk];
            __nv_bfloat16 h = __float2bfloat16_rn(v);
            g_Whi[idx] = h;
            g_Wlo[idx] = __float2bfloat16_rn(v - __bfloat162float(h));
        }
    }
}

// ---------------------------------------------------------------------------
// CSR rowptr from sorted row[]: rowptr[i] = first edge with row >= i.
// ---------------------------------------------------------------------------
__global__ void build_rowptr(const int* __restrict__ row, int E, int Nn)
{
    const int e = blockIdx.x * blockDim.x + threadIdx.x;
    if (e >= E) return;
    const int r = row[e];
    const int prev = (e == 0) ? -1 : row[e - 1];
    for (int j = prev + 1; j <= r; j++) g_rowptr[j] = e;
    if (e == E - 1)
        for (int j = r + 1; j <= Nn; j++) g_rowptr[j] = E;
}

// ---------------------------------------------------------------------------
// Core: acc += Ahi*Bhi + Alo*Bhi + Ahi*Blo over K=128 (resident in smem).
// Tile M=64 x N=128; 8 warps; warp tile 32x32 (warp_m=w&1, warp_n=w>>1).
// ---------------------------------------------------------------------------
__device__ __forceinline__ void mma_all(float acc[2][4][4], uint32_t sbase,
                                        int warp_m, int warp_n, int lane)
{
    const uint32_t AHI = sbase + AHI_E * 2;
    const uint32_t ALO = sbase + ALO_E * 2;
    const uint32_t BHI = sbase + BHI_E * 2;
    const uint32_t BLO = sbase + BLO_E * 2;
    const uint32_t a_off = (uint32_t)((warp_m * 32 + (lane & 15)) * LDROW + ((lane >> 4) << 3)) * 2;
    const uint32_t b_off = (uint32_t)((warp_n * 32 + (lane & 7) + ((lane >> 4) << 3)) * LDROW +
                                      (lane & 8)) * 2;
    #pragma unroll
    for (int ks = 0; ks < 8; ks++) {
        const uint32_t kb = (uint32_t)ks * 32;   // 16 bf16 = 32 B per k-step
        uint32_t aH[2][4], aL[2][4], bH[2][4], bL[2][4];
        #pragma unroll
        for (int mi = 0; mi < 2; mi++)
            ldm_x4(aH[mi], AHI + a_off + kb + (uint32_t)(mi * 16 * LDROW) * 2);
        #pragma unroll
        for (int g = 0; g < 2; g++)
            ldm_x4(bH[g], BHI + b_off + kb + (uint32_t)(g * 16 * LDROW) * 2);
        #pragma unroll
        for (int mi = 0; mi < 2; mi++)
            #pragma unroll
            for (int g = 0; g < 2; g++) {
                mma16816(acc[mi][2 * g],     aH[mi], bH[g]);
                mma16816(acc[mi][2 * g + 1], aH[mi], bH[g] + 2);
            }
        #pragma unroll
        for (int mi = 0; mi < 2; mi++)
            ldm_x4(aL[mi], ALO + a_off + kb + (uint32_t)(mi * 16 * LDROW) * 2);
        #pragma unroll
        for (int mi = 0; mi < 2; mi++)
            #pragma unroll
            for (int g = 0; g < 2; g++) {
                mma16816(acc[mi][2 * g],     aL[mi], bH[g]);
                mma16816(acc[mi][2 * g + 1], aL[mi], bH[g] + 2);
            }
        #pragma unroll
        for (int g = 0; g < 2; g++)
            ldm_x4(bL[g], BLO + b_off + kb + (uint32_t)(g * 16 * LDROW) * 2);
        #pragma unroll
        for (int mi = 0; mi < 2; mi++)
            #pragma unroll
            for (int g = 0; g < 2; g++) {
                mma16816(acc[mi][2 * g],     aH[mi], bL[g]);
                mma16816(acc[mi][2 * g + 1], aH[mi], bL[g] + 2);
            }
    }
}

// async-load one GEMM tile pair: A (64x128 hi/lo) + B (128x128 hi/lo)
__device__ __forceinline__ void load_tiles(uint32_t sbase, int tid,
                                           const __nv_bfloat16* Ahi, const __nv_bfloat16* Alo,
                                           const __nv_bfloat16* Bhi, const __nv_bfloat16* Blo)
{
    #pragma unroll
    for (int c = 0; c < 1024; c += 256) {
        const int cc = c + tid;
        const int r = cc >> 4, col = (cc & 15) * 8;
        cp16(sbase + (uint32_t)(AHI_E + r * LDROW + col) * 2, Ahi + r * 128 + col);
        cp16(sbase + (uint32_t)(ALO_E + r * LDROW + col) * 2, Alo + r * 128 + col);
    }
    #pragma unroll
    for (int c = 0; c < 2048; c += 256) {
        const int cc = c + tid;
        const int r = cc >> 4, col = (cc & 15) * 8;
        cp16(sbase + (uint32_t)(BHI_E + r * LDROW + col) * 2, Bhi + r * 128 + col);
        cp16(sbase + (uint32_t)(BLO_E + r * LDROW + col) * 2, Blo + r * 128 + col);
    }
    CP_WAIT_ALL();
}

// ---------------------------------------------------------------------------
// QKV projection: grid = (M-tiles, 3). Head-major permuted outputs; Q * 0.5.
// ---------------------------------------------------------------------------
__global__ __launch_bounds__(256, 2) void qkv_tc(
    const float* __restrict__ bq, const float* __restrict__ bk,
    const float* __restrict__ bv, int Nn)
{
    extern __shared__ __nv_bfloat16 sm[];
    const uint32_t sbase = smem_u32(sm);
    const int tid = threadIdx.x;
    const int lane = tid & 31;
    const int w = tid >> 5;
    const int warp_m = w & 1;
    const int warp_n = w >> 1;
    const int m0 = blockIdx.x * 64;
    const int o = blockIdx.y;

    load_tiles(sbase, tid,
               g_Xhi + (size_t)m0 * 128, g_Xlo + (size_t)m0 * 128,
               g_Whi + o * 16384, g_Wlo + o * 16384);
    __syncthreads();

    float acc[2][4][4];
    #pragma unroll
    for (int mi = 0; mi < 2; mi++)
        #pragma unroll
        for (int nb = 0; nb < 4; nb++)
            #pragma unroll
            for (int j = 0; j < 4; j++) acc[mi][nb][j] = 0.f;

    mma_all(acc, sbase, warp_m, warp_n, lane);

    float* dst = (o == 0) ? g_Q : (o == 1) ? g_K : g_V;
    const float alpha = (o == 0) ? 0.5f : 1.0f;
    const float* bias = (o == 0) ? bq : (o == 1) ? bk : bv;

    #pragma unroll
    for (int mi = 0; mi < 2; mi++) {
        const int mrow = m0 + warp_m * 32 + mi * 16 + (lane >> 2);
        #pragma unroll
        for (int nb = 0; nb < 4; nb++) {
            const int f0 = warp_n * 32 + nb * 8 + (lane & 3) * 2;
            const int f1 = f0 + 1;
            const int p0 = (f0 & 3) * 32 + (f0 >> 2);
            const int p1 = (f1 & 3) * 32 + (f1 >> 2);
            const float b0 = __ldg(&bias[f0]);
            const float b1 = __ldg(&bias[f1]);
            if (mrow < Nn) {
                dst[(size_t)mrow * 128 + p0] = (acc[mi][nb][0] + b0) * alpha;
                dst[(size_t)mrow * 128 + p1] = (acc[mi][nb][1] + b1) * alpha;
            }
            if (mrow + 8 < Nn) {
                dst[(size_t)(mrow + 8) * 128 + p0] = (acc[mi][nb][2] + b0) * alpha;
                dst[(size_t)(mrow + 8) * 128 + p1] = (acc[mi][nb][3] + b1) * alpha;
            }
        }
    }
}

// ---------------------------------------------------------------------------
// Output projection: A = Y (bf16 hi/lo from edge_attn), B = Wo (pre-permuted).
// ---------------------------------------------------------------------------
__global__ __launch_bounds__(256, 2) void out_tc(
    const float* __restrict__ bo, float* __restrict__ out, int Nn)
{
    extern __shared__ __nv_bfloat16 sm[];
    const uint32_t sbase = smem_u32(sm);
    const int tid = threadIdx.x;
    const int lane = tid & 31;
    const int w = tid >> 5;
    const int warp_m = w & 1;
    const int warp_n = w >> 1;
    const int m0 = blockIdx.x * 64;

    load_tiles(sbase, tid,
               g_Yhi + (size_t)m0 * 128, g_Ylo + (size_t)m0 * 128,
               g_Whi + 3 * 16384, g_Wlo + 3 * 16384);
    __syncthreads();

    float acc[2][4][4];
    #pragma unroll
    for (int mi = 0; mi < 2; mi++)
        #pragma unroll
        for (int nb = 0; nb < 4; nb++)
            #pragma unroll
            for (int j = 0; j < 4; j++) acc[mi][nb][j] = 0.f;

    mma_all(acc, sbase, warp_m, warp_n, lane);

    #pragma unroll
    for (int mi = 0; mi < 2; mi++) {
        const int mrow = m0 + warp_m * 32 + mi * 16 + (lane >> 2);
        #pragma unroll
        for (int nb = 0; nb < 4; nb++) {
            const int f0 = warp_n * 32 + nb * 8 + (lane & 3) * 2;
            const float b0 = __ldg(&bo[f0]);
            const float b1 = __ldg(&bo[f0 + 1]);
            if (mrow < Nn) {
                float2 v = make_float2(acc[mi][nb][0] + b0, acc[mi][nb][1] + b1);
                *(float2*)&out[(size_t)mrow * 128 + f0] = v;
            }
            if (mrow + 8 < Nn) {
                float2 v = make_float2(acc[mi][nb][2] + b0, acc[mi][nb][3] + b1);
                *(float2*)&out[(size_t)(mrow + 8) * 128 + f0] = v;
            }
        }
    }
}

// ---------------------------------------------------------------------------
// Fused edge attention v2: one warp per node, rowptr lookup, NO max-subtract
// (softmax is shift-invariant; |s| <~ 16 so exp() is safe in fp32),
// unroll-by-4 with batched K/V loads and independent shfl trees.
// Head h = lane>>3; each lane owns dims [lane*4, lane*4+4).
// ---------------------------------------------------------------------------
__device__ __forceinline__ float head_dot(float4 a, float4 b) {
    float s = a.x * b.x + a.y * b.y + a.z * b.z + a.w * b.w;
    s += __shfl_xor_sync(0xffffffffu, s, 1);
    s += __shfl_xor_sync(0xffffffffu, s, 2);
    s += __shfl_xor_sync(0xffffffffu, s, 4);
    return s;
}

__global__ __launch_bounds__(256) void edge_attn(const int* __restrict__ col, int Nn)
{
    const int i = (blockIdx.x * blockDim.x + threadIdx.x) >> 5;
    const int lane = threadIdx.x & 31;
    if (i >= Nn) return;

    const int start = g_rowptr[i];
    const int end   = g_rowptr[i + 1];

    const float4 qv = *(const float4*)&g_Q[(size_t)i * 128 + lane * 4];

    float l = 0.f;
    float4 acc = make_float4(0.f, 0.f, 0.f, 0.f);

    int e = start;
    for (; e + 4 <= end; e += 4) {
        const int c0 = __ldg(&col[e]);
        const int c1 = __ldg(&col[e + 1]);
        const int c2 = __ldg(&col[e + 2]);
        const int c3 = __ldg(&col[e + 3]);
        const float4 k0 = *(const float4*)&g_K[(size_t)c0 * 128 + lane * 4];
        const float4 k1 = *(const float4*)&g_K[(size_t)c1 * 128 + lane * 4];
        const float4 k2 = *(const float4*)&g_K[(size_t)c2 * 128 + lane * 4];
        const float4 k3 = *(const float4*)&g_K[(size_t)c3 * 128 + lane * 4];
        const float4 v0 = *(const float4*)&g_V[(size_t)c0 * 128 + lane * 4];
        const float4 v1 = *(const float4*)&g_V[(size_t)c1 * 128 + lane * 4];
        const float4 v2 = *(const float4*)&g_V[(size_t)c2 * 128 + lane * 4];
        const float4 v3 = *(const float4*)&g_V[(size_t)c3 * 128 + lane * 4];

        // 4 independent dot/shfl trees — interleaved by the scheduler
        float s0 = qv.x * k0.x + qv.y * k0.y + qv.z * k0.z + qv.w * k0.w;
        float s1 = qv.x * k1.x + qv.y * k1.y + qv.z * k1.z + qv.w * k1.w;
        float s2 = qv.x * k2.x + qv.y * k2.y + qv.z * k2.z + qv.w * k2.w;
        float s3 = qv.x * k3.x + qv.y * k3.y + qv.z * k3.z + qv.w * k3.w;
        s0 += __shfl_xor_sync(0xffffffffu, s0, 1);
        s1 += __shfl_xor_sync(0xffffffffu, s1, 1);
        s2 += __shfl_xor_sync(0xffffffffu, s2, 1);
        s3 += __shfl_xor_sync(0xffffffffu, s3, 1);
        s0 += __shfl_xor_sync(0xffffffffu, s0, 2);
        s1 += __shfl_xor_sync(0xffffffffu, s1, 2);
        s2 += __shfl_xor_sync(0xffffffffu, s2, 2);
        s3 += __shfl_xor_sync(0xffffffffu, s3, 2);
        s0 += __shfl_xor_sync(0xffffffffu, s0, 4);
        s1 += __shfl_xor_sync(0xffffffffu, s1, 4);
        s2 += __shfl_xor_sync(0xffffffffu, s2, 4);
        s3 += __shfl_xor_sync(0xffffffffu, s3, 4);

        const float w0 = __expf(s0);
        const float w1 = __expf(s1);
        const float w2 = __expf(s2);
        const float w3 = __expf(s3);
        l += (w0 + w1) + (w2 + w3);

        acc.x += w0 * v0.x + w1 * v1.x + w2 * v2.x + w3 * v3.x;
        acc.y += w0 * v0.y + w1 * v1.y + w2 * v2.y + w3 * v3.y;
        acc.z += w0 * v0.z + w1 * v1.z + w2 * v2.z + w3 * v3.z;
        acc.w += w0 * v0.w + w1 * v1.w + w2 * v2.w + w3 * v3.w;
    }
    for (; e < end; e++) {
        const int c = __ldg(&col[e]);
        const float4 kv = *(const float4*)&g_K[(size_t)c * 128 + lane * 4];
        const float4 vv = *(const float4*)&g_V[(size_t)c * 128 + lane * 4];
        const float wgt = __expf(head_dot(qv, kv));
        l += wgt;
        acc.x += wgt * vv.x;
        acc.y += wgt * vv.y;
        acc.z += wgt * vv.z;
        acc.w += wgt * vv.w;
    }

    const float inv = (l > 0.f) ? (1.f / l) : 0.f;
    float4 o;
    o.x = acc.x * inv; o.y = acc.y * inv; o.z = acc.z * inv; o.w = acc.w * inv;

    // split-store Y as bf16 hi/lo for out_tc
    __nv_bfloat16 h0 = __float2bfloat16_rn(o.x), h1 = __float2bfloat16_rn(o.y);
    __nv_bfloat16 h2 = __float2bfloat16_rn(o.z), h3 = __float2bfloat16_rn(o.w);
    __nv_bfloat162 hp0, hp1, lp0, lp1;
    hp0.x = h0; hp0.y = h1; hp1.x = h2; hp1.y = h3;
    lp0.x = __float2bfloat16_rn(o.x - __bfloat162float(h0));
    lp0.y = __float2bfloat16_rn(o.y - __bfloat162float(h1));
    lp1.x = __float2bfloat16_rn(o.z - __bfloat162float(h2));
    lp1.y = __float2bfloat16_rn(o.w - __bfloat162float(h3));
    const size_t base = (size_t)i * 128 + lane * 4;
    *(__nv_bfloat162*)&g_Yhi[base]     = hp0;
    *(__nv_bfloat162*)&g_Yhi[base + 2] = hp1;
    *(__nv_bfloat162*)&g_Ylo[base]     = lp0;
    *(__nv_bfloat162*)&g_Ylo[base + 2] = lp1;
}

// ---------------------------------------------------------------------------
extern "C" void kernel_launch(void* const* d_in, const int* in_sizes, int n_in,
                              void* d_out, int out_size)
{
    const float* x  = (const float*)d_in[0];
    const int*   row = (const int*)d_in[1];
    const int*   col = (const int*)d_in[2];
    const float* Wq = (const float*)d_in[3];
    const float* bq = (const float*)d_in[4];
    const float* Wk = (const float*)d_in[5];
    const float* bk = (const float*)d_in[6];
    const float* Wv = (const float*)d_in[7];
    const float* bv = (const float*)d_in[8];
    const float* Wo = (const float*)d_in[9];
    const float* bo = (const float*)d_in[10];

    const int Nn = in_sizes[0] / 128;
    const int E  = in_sizes[1];
    const int t64 = (Nn + 63) / 64;

    cudaFuncSetAttribute(qkv_tc, cudaFuncAttributeMaxDynamicSharedMemorySize, SMEM_BYTES);
    cudaFuncSetAttribute(out_tc, cudaFuncAttributeMaxDynamicSharedMemorySize, SMEM_BYTES);

    convert_all<<<dim3((Nn * 32 + 255) / 256, 2), 256>>>(x, Wq, Wk, Wv, Wo, Nn);
    build_rowptr<<<(E + 255) / 256, 256>>>(row, E, Nn);

    qkv_tc<<<dim3(t64, 3), 256, SMEM_BYTES>>>(bq, bk, bv, Nn);

    const int edge_blocks = (Nn * 32 + 255) / 256;
    edge_attn<<<edge_blocks, 256>>>(col, Nn);

    out_tc<<<dim3(t64, 1), 256, SMEM_BYTES>>>(bo, (float*)d_out, Nn);
}

// round 6
// speedup vs baseline: 1.8979x; 1.0622x over previous
#include <cuda_runtime.h>
#include <cuda_bf16.h>
#include <cstdint>

// Problem constants: N=100000, E=800000, D=128, H=4, DH=32
#define MAX_N 100096
#define ND ((size_t)MAX_N * 128)

__device__ float g_Q[ND];
__device__ float g_K[ND];
__device__ float g_V[ND];
__device__ __nv_bfloat16 g_Xhi[ND], g_Xlo[ND];
__device__ __nv_bfloat16 g_Yhi[ND], g_Ylo[ND];
__device__ __nv_bfloat16 g_Whi[4 * 16384], g_Wlo[4 * 16384];  // Wq,Wk,Wv,Wo(K-permuted)
__device__ int g_rowptr[MAX_N + 1];

// smem layout (bf16 elements), rows padded to 136 for conflict-free ldmatrix
#define LDROW 136
#define A_ROWS 32
#define A_PART (A_ROWS * LDROW)       // 4352
#define A_BUF  (2 * A_PART)           // hi+lo per buffer: 8704
#define B_HI_E (2 * A_BUF)            // 17408
#define B_LO_E (B_HI_E + 128 * LDROW) // 34816
#define SMEM_ELEMS (B_LO_E + 128 * LDROW)  // 52224
#define SMEM_BYTES (SMEM_ELEMS * 2)        // 104448

// ---------------------------------------------------------------------------
__device__ __forceinline__ uint32_t smem_u32(const void* p) {
    uint32_t a;
    asm("{ .reg .u64 t; cvta.to.shared.u64 t, %1; cvt.u32.u64 %0, t; }" : "=r"(a) : "l"(p));
    return a;
}
__device__ __forceinline__ void ldm_x4(uint32_t* r, uint32_t addr) {
    asm volatile("ldmatrix.sync.aligned.m8n8.x4.shared.b16 {%0,%1,%2,%3}, [%4];"
                 : "=r"(r[0]), "=r"(r[1]), "=r"(r[2]), "=r"(r[3]) : "r"(addr));
}
__device__ __forceinline__ void mma16816(float* d, const uint32_t* a, const uint32_t* b) {
    asm volatile(
        "mma.sync.aligned.m16n8k16.row.col.f32.bf16.bf16.f32 "
        "{%0,%1,%2,%3},{%4,%5,%6,%7},{%8,%9},{%0,%1,%2,%3};"
        : "+f"(d[0]), "+f"(d[1]), "+f"(d[2]), "+f"(d[3])
        : "r"(a[0]), "r"(a[1]), "r"(a[2]), "r"(a[3]), "r"(b[0]), "r"(b[1]));
}
__device__ __forceinline__ void cp16(uint32_t saddr, const void* gptr) {
    asm volatile("cp.async.ca.shared.global [%0], [%1], 16;" :: "r"(saddr), "l"(gptr));
}
#define CP_COMMIT() asm volatile("cp.async.commit_group;" ::: "memory")
#define CP_WAIT0()  asm volatile("cp.async.wait_group 0;" ::: "memory")

// ---------------------------------------------------------------------------
// One-shot conversion: x -> g_Xhi/lo ; {Wq,Wk,Wv,Wo(K-perm)} -> g_Whi/lo
// ---------------------------------------------------------------------------
__global__ void convert_all(const float* __restrict__ x,
                            const float* __restrict__ Wq, const float* __restrict__ Wk,
                            const float* __restrict__ Wv, const float* __restrict__ Wo,
                            int Nn)
{
    const int idx = blockIdx.x * blockDim.x + threadIdx.x;
    if (blockIdx.y == 0) {
        const int total = Nn * 32;                 // float4s in x
        if (idx < total) {
            float4 v = ((const float4*)x)[idx];
            __nv_bfloat16 h0 = __float2bfloat16_rn(v.x), h1 = __float2bfloat16_rn(v.y);
            __nv_bfloat16 h2 = __float2bfloat16_rn(v.z), h3 = __float2bfloat16_rn(v.w);
            __nv_bfloat162 hp0, hp1, lp0, lp1;
            hp0.x = h0; hp0.y = h1; hp1.x = h2; hp1.y = h3;
            lp0.x = __float2bfloat16_rn(v.x - __bfloat162float(h0));
            lp0.y = __float2bfloat16_rn(v.y - __bfloat162float(h1));
            lp1.x = __float2bfloat16_rn(v.z - __bfloat162float(h2));
            lp1.y = __float2bfloat16_rn(v.w - __bfloat162float(h3));
            *(__nv_bfloat162*)&g_Xhi[idx * 4]     = hp0;
            *(__nv_bfloat162*)&g_Xhi[idx * 4 + 2] = hp1;
            *(__nv_bfloat162*)&g_Xlo[idx * 4]     = lp0;
            *(__nv_bfloat162*)&g_Xlo[idx * 4 + 2] = lp1;
        }
    } else {
        if (idx < 4 * 16384) {
            const int mat = idx >> 14, e = idx & 16383;
            const int f = e >> 7, k = e & 127;
            const float* W = (mat == 0) ? Wq : (mat == 1) ? Wk : (mat == 2) ? Wv : Wo;
            const int kk = (mat == 3) ? ((k & 31) * 4 + (k >> 5)) : k;  // undo head-major for Wo
            const float v = W[f * 128 + kk];
            __nv_bfloat16 h = __float2bfloat16_rn(v);
            g_Whi[idx] = h;
            g_Wlo[idx] = __float2bfloat16_rn(v - __bfloat162float(h));
        }
    }
}

// ---------------------------------------------------------------------------
// CSR rowptr from sorted row[]
// ---------------------------------------------------------------------------
__global__ void build_rowptr(const int* __restrict__ row, int E, int Nn)
{
    const int e = blockIdx.x * blockDim.x + threadIdx.x;
    if (e >= E) return;
    const int r = row[e];
    const int prev = (e == 0) ? -1 : row[e - 1];
    for (int j = prev + 1; j <= r; j++) g_rowptr[j] = e;
    if (e == E - 1)
        for (int j = r + 1; j <= Nn; j++) g_rowptr[j] = E;
}

// ---------------------------------------------------------------------------
// Shared GEMM pieces: persistent B in smem, A tiles (32 rows) double-buffered.
// 8 warps: warp_m = w&1 (2 x 16 rows), warp_n = w>>1 (4 x 32 cols).
// ---------------------------------------------------------------------------
__device__ __forceinline__ void load_B(uint32_t sbase, int tid,
                                       const __nv_bfloat16* Bhi, const __nv_bfloat16* Blo)
{
    #pragma unroll
    for (int c = 0; c < 2048; c += 256) {
        const int cc = c + tid;
        const int r = cc >> 4, col = (cc & 15) * 8;
        cp16(sbase + (uint32_t)(B_HI_E + r * LDROW + col) * 2, Bhi + r * 128 + col);
        cp16(sbase + (uint32_t)(B_LO_E + r * LDROW + col) * 2, Blo + r * 128 + col);
    }
}
__device__ __forceinline__ void load_A(uint32_t sbase, int buf, int tid,
                                       const __nv_bfloat16* Ahi, const __nv_bfloat16* Alo,
                                       int m0)
{
    const uint32_t abase = (uint32_t)(buf * A_BUF);
    #pragma unroll
    for (int c = 0; c < 512; c += 256) {
        const int cc = c + tid;
        const int r = cc >> 4, col = (cc & 15) * 8;
        cp16(sbase + (abase + (uint32_t)(r * LDROW + col)) * 2,
             Ahi + (size_t)(m0 + r) * 128 + col);
        cp16(sbase + (abase + (uint32_t)(A_PART + r * LDROW + col)) * 2,
             Alo + (size_t)(m0 + r) * 128 + col);
    }
}

// acc[4][4]: nb = g*2+half over 32 output cols; warp tile 16x32.
__device__ __forceinline__ void mma_tile(float acc[4][4], uint32_t sbase, int buf,
                                         int warp_m, int warp_n, int lane)
{
    const uint32_t AHI = sbase + (uint32_t)(buf * A_BUF) * 2;
    const uint32_t ALO = AHI + (uint32_t)A_PART * 2;
    const uint32_t BHI = sbase + (uint32_t)B_HI_E * 2;
    const uint32_t BLO = sbase + (uint32_t)B_LO_E * 2;
    const uint32_t a_off = (uint32_t)((warp_m * 16 + (lane & 15)) * LDROW + ((lane >> 4) << 3)) * 2;
    const uint32_t b_off = (uint32_t)((warp_n * 32 + (lane & 7) + ((lane >> 4) << 3)) * LDROW +
                                      (lane & 8)) * 2;
    #pragma unroll
    for (int ks = 0; ks < 8; ks++) {
        const uint32_t kb = (uint32_t)ks * 32;   // 16 bf16 = 32 B
        uint32_t aH[4], aL[4], bH[2][4], bL[2][4];
        ldm_x4(aH, AHI + a_off + kb);
        #pragma unroll
        for (int g = 0; g < 2; g++)
            ldm_x4(bH[g], BHI + b_off + kb + (uint32_t)(g * 16 * LDROW) * 2);
        #pragma unroll
        for (int g = 0; g < 2; g++) {
            mma16816(acc[2 * g],     aH, bH[g]);
            mma16816(acc[2 * g + 1], aH, bH[g] + 2);
        }
        ldm_x4(aL, ALO + a_off + kb);
        #pragma unroll
        for (int g = 0; g < 2; g++) {
            mma16816(acc[2 * g],     aL, bH[g]);
            mma16816(acc[2 * g + 1], aL, bH[g] + 2);
        }
        #pragma unroll
        for (int g = 0; g < 2; g++)
            ldm_x4(bL[g], BLO + b_off + kb + (uint32_t)(g * 16 * LDROW) * 2);
        #pragma unroll
        for (int g = 0; g < 2; g++) {
            mma16816(acc[2 * g],     aH, bL[g]);
            mma16816(acc[2 * g + 1], aH, bL[g] + 2);
        }
    }
}

// ---------------------------------------------------------------------------
// Persistent QKV projection: grid=(99,3); B resident; A tiles streamed.
// ---------------------------------------------------------------------------
__global__ __launch_bounds__(256, 2) void qkv_tc(
    const float* __restrict__ bq, const float* __restrict__ bk,
    const float* __restrict__ bv, int Nn, int ntiles)
{
    extern __shared__ __nv_bfloat16 sm[];
    const uint32_t sbase = smem_u32(sm);
    const int tid = threadIdx.x;
    const int lane = tid & 31;
    const int w = tid >> 5;
    const int warp_m = w & 1;
    const int warp_n = w >> 1;
    const int o = blockIdx.y;

    float* dst = (o == 0) ? g_Q : (o == 1) ? g_K : g_V;
    const float alpha = (o == 0) ? 0.5f : 1.0f;
    const float* bias = (o == 0) ? bq : (o == 1) ? bk : bv;

    load_B(sbase, tid, g_Whi + o * 16384, g_Wlo + o * 16384);
    int t = blockIdx.x;
    if (t < ntiles) load_A(sbase, 0, tid, g_Xhi, g_Xlo, t * A_ROWS);
    CP_COMMIT();

    int buf = 0;
    for (; t < ntiles; t += gridDim.x) {
        CP_WAIT0();
        __syncthreads();
        const int tn = t + gridDim.x;
        if (tn < ntiles) {
            load_A(sbase, buf ^ 1, tid, g_Xhi, g_Xlo, tn * A_ROWS);
            CP_COMMIT();
        }

        float acc[4][4];
        #pragma unroll
        for (int nb = 0; nb < 4; nb++)
            #pragma unroll
            for (int j = 0; j < 4; j++) acc[nb][j] = 0.f;

        mma_tile(acc, sbase, buf, warp_m, warp_n, lane);

        const int mrow = t * A_ROWS + warp_m * 16 + (lane >> 2);
        #pragma unroll
        for (int nb = 0; nb < 4; nb++) {
            const int f0 = warp_n * 32 + nb * 8 + (lane & 3) * 2;
            const int f1 = f0 + 1;
            const int p0 = (f0 & 3) * 32 + (f0 >> 2);
            const int p1 = (f1 & 3) * 32 + (f1 >> 2);
            const float b0 = __ldg(&bias[f0]);
            const float b1 = __ldg(&bias[f1]);
            if (mrow < Nn) {
                dst[(size_t)mrow * 128 + p0] = (acc[nb][0] + b0) * alpha;
                dst[(size_t)mrow * 128 + p1] = (acc[nb][1] + b1) * alpha;
            }
            if (mrow + 8 < Nn) {
                dst[(size_t)(mrow + 8) * 128 + p0] = (acc[nb][2] + b0) * alpha;
                dst[(size_t)(mrow + 8) * 128 + p1] = (acc[nb][3] + b1) * alpha;
            }
        }
        buf ^= 1;
    }
}

// ---------------------------------------------------------------------------
// Persistent output projection: B = Wo (pre-permuted), A = Y hi/lo.
// ---------------------------------------------------------------------------
__global__ __launch_bounds__(256, 2) void out_tc(
    const float* __restrict__ bo, float* __restrict__ out, int Nn, int ntiles)
{
    extern __shared__ __nv_bfloat16 sm[];
    const uint32_t sbase = smem_u32(sm);
    const int tid = threadIdx.x;
    const int lane = tid & 31;
    const int w = tid >> 5;
    const int warp_m = w & 1;
    const int warp_n = w >> 1;

    load_B(sbase, tid, g_Whi + 3 * 16384, g_Wlo + 3 * 16384);
    int t = blockIdx.x;
    if (t < ntiles) load_A(sbase, 0, tid, g_Yhi, g_Ylo, t * A_ROWS);
    CP_COMMIT();

    int buf = 0;
    for (; t < ntiles; t += gridDim.x) {
        CP_WAIT0();
        __syncthreads();
        const int tn = t + gridDim.x;
        if (tn < ntiles) {
            load_A(sbase, buf ^ 1, tid, g_Yhi, g_Ylo, tn * A_ROWS);
            CP_COMMIT();
        }

        float acc[4][4];
        #pragma unroll
        for (int nb = 0; nb < 4; nb++)
            #pragma unroll
            for (int j = 0; j < 4; j++) acc[nb][j] = 0.f;

        mma_tile(acc, sbase, buf, warp_m, warp_n, lane);

        const int mrow = t * A_ROWS + warp_m * 16 + (lane >> 2);
        #pragma unroll
        for (int nb = 0; nb < 4; nb++) {
            const int f0 = warp_n * 32 + nb * 8 + (lane & 3) * 2;
            const float b0 = __ldg(&bo[f0]);
            const float b1 = __ldg(&bo[f0 + 1]);
            if (mrow < Nn) {
                float2 v = make_float2(acc[nb][0] + b0, acc[nb][1] + b1);
                *(float2*)&out[(size_t)mrow * 128 + f0] = v;
            }
            if (mrow + 8 < Nn) {
                float2 v = make_float2(acc[nb][2] + b0, acc[nb][3] + b1);
                *(float2*)&out[(size_t)(mrow + 8) * 128 + f0] = v;
            }
        }
        buf ^= 1;
    }
}

// ---------------------------------------------------------------------------
// Fused edge attention: one warp per node, rowptr lookup, no max-subtract,
// unroll-by-4 batched loads. (At the combined memory roofline — unchanged.)
// ---------------------------------------------------------------------------
__device__ __forceinline__ float head_dot(float4 a, float4 b) {
    float s = a.x * b.x + a.y * b.y + a.z * b.z + a.w * b.w;
    s += __shfl_xor_sync(0xffffffffu, s, 1);
    s += __shfl_xor_sync(0xffffffffu, s, 2);
    s += __shfl_xor_sync(0xffffffffu, s, 4);
    return s;
}

__global__ __launch_bounds__(256) void edge_attn(const int* __restrict__ col, int Nn)
{
    const int i = (blockIdx.x * blockDim.x + threadIdx.x) >> 5;
    const int lane = threadIdx.x & 31;
    if (i >= Nn) return;

    const int start = g_rowptr[i];
    const int end   = g_rowptr[i + 1];

    const float4 qv = *(const float4*)&g_Q[(size_t)i * 128 + lane * 4];

    float l = 0.f;
    float4 acc = make_float4(0.f, 0.f, 0.f, 0.f);

    int e = start;
    for (; e + 4 <= end; e += 4) {
        const int c0 = __ldg(&col[e]);
        const int c1 = __ldg(&col[e + 1]);
        const int c2 = __ldg(&col[e + 2]);
        const int c3 = __ldg(&col[e + 3]);
        const float4 k0 = *(const float4*)&g_K[(size_t)c0 * 128 + lane * 4];
        const float4 k1 = *(const float4*)&g_K[(size_t)c1 * 128 + lane * 4];
        const float4 k2 = *(const float4*)&g_K[(size_t)c2 * 128 + lane * 4];
        const float4 k3 = *(const float4*)&g_K[(size_t)c3 * 128 + lane * 4];
        const float4 v0 = *(const float4*)&g_V[(size_t)c0 * 128 + lane * 4];
        const float4 v1 = *(const float4*)&g_V[(size_t)c1 * 128 + lane * 4];
        const float4 v2 = *(const float4*)&g_V[(size_t)c2 * 128 + lane * 4];
        const float4 v3 = *(const float4*)&g_V[(size_t)c3 * 128 + lane * 4];

        float s0 = qv.x * k0.x + qv.y * k0.y + qv.z * k0.z + qv.w * k0.w;
        float s1 = qv.x * k1.x + qv.y * k1.y + qv.z * k1.z + qv.w * k1.w;
        float s2 = qv.x * k2.x + qv.y * k2.y + qv.z * k2.z + qv.w * k2.w;
        float s3 = qv.x * k3.x + qv.y * k3.y + qv.z * k3.z + qv.w * k3.w;
        s0 += __shfl_xor_sync(0xffffffffu, s0, 1);
        s1 += __shfl_xor_sync(0xffffffffu, s1, 1);
        s2 += __shfl_xor_sync(0xffffffffu, s2, 1);
        s3 += __shfl_xor_sync(0xffffffffu, s3, 1);
        s0 += __shfl_xor_sync(0xffffffffu, s0, 2);
        s1 += __shfl_xor_sync(0xffffffffu, s1, 2);
        s2 += __shfl_xor_sync(0xffffffffu, s2, 2);
        s3 += __shfl_xor_sync(0xffffffffu, s3, 2);
        s0 += __shfl_xor_sync(0xffffffffu, s0, 4);
        s1 += __shfl_xor_sync(0xffffffffu, s1, 4);
        s2 += __shfl_xor_sync(0xffffffffu, s2, 4);
        s3 += __shfl_xor_sync(0xffffffffu, s3, 4);

        const float w0 = __expf(s0);
        const float w1 = __expf(s1);
        const float w2 = __expf(s2);
        const float w3 = __expf(s3);
        l += (w0 + w1) + (w2 + w3);

        acc.x += w0 * v0.x + w1 * v1.x + w2 * v2.x + w3 * v3.x;
        acc.y += w0 * v0.y + w1 * v1.y + w2 * v2.y + w3 * v3.y;
        acc.z += w0 * v0.z + w1 * v1.z + w2 * v2.z + w3 * v3.z;
        acc.w += w0 * v0.w + w1 * v1.w + w2 * v2.w + w3 * v3.w;
    }
    for (; e < end; e++) {
        const int c = __ldg(&col[e]);
        const float4 kv = *(const float4*)&g_K[(size_t)c * 128 + lane * 4];
        const float4 vv = *(const float4*)&g_V[(size_t)c * 128 + lane * 4];
        const float wgt = __expf(head_dot(qv, kv));
        l += wgt;
        acc.x += wgt * vv.x;
        acc.y += wgt * vv.y;
        acc.z += wgt * vv.z;
        acc.w += wgt * vv.w;
    }

    const float inv = (l > 0.f) ? (1.f / l) : 0.f;
    float4 o;
    o.x = acc.x * inv; o.y = acc.y * inv; o.z = acc.z * inv; o.w = acc.w * inv;

    __nv_bfloat16 h0 = __float2bfloat16_rn(o.x), h1 = __float2bfloat16_rn(o.y);
    __nv_bfloat16 h2 = __float2bfloat16_rn(o.z), h3 = __float2bfloat16_rn(o.w);
    __nv_bfloat162 hp0, hp1, lp0, lp1;
    hp0.x = h0; hp0.y = h1; hp1.x = h2; hp1.y = h3;
    lp0.x = __float2bfloat16_rn(o.x - __bfloat162float(h0));
    lp0.y = __float2bfloat16_rn(o.y - __bfloat162float(h1));
    lp1.x = __float2bfloat16_rn(o.z - __bfloat162float(h2));
    lp1.y = __float2bfloat16_rn(o.w - __bfloat162float(h3));
    const size_t base = (size_t)i * 128 + lane * 4;
    *(__nv_bfloat162*)&g_Yhi[base]     = hp0;
    *(__nv_bfloat162*)&g_Yhi[base + 2] = hp1;
    *(__nv_bfloat162*)&g_Ylo[base]     = lp0;
    *(__nv_bfloat162*)&g_Ylo[base + 2] = lp1;
}

// ---------------------------------------------------------------------------
extern "C" void kernel_launch(void* const* d_in, const int* in_sizes, int n_in,
                              void* d_out, int out_size)
{
    const float* x  = (const float*)d_in[0];
    const int*   row = (const int*)d_in[1];
    const int*   col = (const int*)d_in[2];
    const float* Wq = (const float*)d_in[3];
    const float* bq = (const float*)d_in[4];
    const float* Wk = (const float*)d_in[5];
    const float* bk = (const float*)d_in[6];
    const float* Wv = (const float*)d_in[7];
    const float* bv = (const float*)d_in[8];
    const float* Wo = (const float*)d_in[9];
    const float* bo = (const float*)d_in[10];

    const int Nn = in_sizes[0] / 128;
    const int E  = in_sizes[1];
    const int ntiles = (Nn + A_ROWS - 1) / A_ROWS;

    cudaFuncSetAttribute(qkv_tc, cudaFuncAttributeMaxDynamicSharedMemorySize, SMEM_BYTES);
    cudaFuncSetAttribute(out_tc, cudaFuncAttributeMaxDynamicSharedMemorySize, SMEM_BYTES);

    convert_all<<<dim3((Nn * 32 + 255) / 256, 2), 256>>>(x, Wq, Wk, Wv, Wo, Nn);
    build_rowptr<<<(E + 255) / 256, 256>>>(row, E, Nn);

    qkv_tc<<<dim3(99, 3), 256, SMEM_BYTES>>>(bq, bk, bv, Nn, ntiles);

    const int edge_blocks = (Nn * 32 + 255) / 256;
    edge_attn<<<edge_blocks, 256>>>(col, Nn);

    out_tc<<<dim3(296, 1), 256, SMEM_BYTES>>>(bo, (float*)d_out, Nn, ntiles);
}